// round 13
// baseline (speedup 1.0000x reference)
#include <cuda_runtime.h>
#include <cuda_bf16.h>
#include <cuda_fp16.h>
#include <cstdint>

#define NN 50000
#define EE 800000
#define CH 256
#define PAD_M 50048          // 391 * 128

// ---- scratch (device globals; no allocation allowed) ----
__device__ __align__(16) __half g_xwh[(size_t)NN * CH];            // x @ W (25.6 MB, fp16)
__device__ int   g_deg[NN];
__device__ int   g_off[NN + 1];
__device__ int   g_cur[NN];
__device__ __align__(16) int2 g_epack[EE];                         // (src, val)
__device__ __align__(16) __nv_bfloat16 g_xhi[(size_t)PAD_M * CH];  // 25.6 MB
__device__ __align__(16) __nv_bfloat16 g_xlo[(size_t)PAD_M * CH];  // 25.6 MB
__device__ __align__(16) __nv_bfloat16 g_wthi[CH * CH];            // W^T hi [n][k]
__device__ __align__(16) __nv_bfloat16 g_wtlo[CH * CH];            // W^T lo [n][k]

// =============================================================== helpers
__device__ __forceinline__ uint32_t smem_u32(const void* p) {
    uint32_t a;
    asm("{ .reg .u64 t; cvta.to.shared.u64 t, %1; cvt.u32.u64 %0, t; }"
        : "=r"(a) : "l"(p));
    return a;
}

__device__ __forceinline__ void cp_async16(uint32_t s, const void* g) {
    asm volatile("cp.async.cg.shared.global [%0], [%1], 16;" :: "r"(s), "l"(g));
}
__device__ __forceinline__ void cp_commit() {
    asm volatile("cp.async.commit_group;" ::: "memory");
}
template <int N>
__device__ __forceinline__ void cp_wait() {
    asm volatile("cp.async.wait_group %0;" :: "n"(N) : "memory");
}

__device__ __forceinline__ void ldsm_x4(uint32_t* r, uint32_t addr) {
    asm volatile("ldmatrix.sync.aligned.m8n8.x4.shared.b16 {%0,%1,%2,%3}, [%4];"
                 : "=r"(r[0]), "=r"(r[1]), "=r"(r[2]), "=r"(r[3]) : "r"(addr));
}

__device__ __forceinline__ uint4 lds128(uint32_t addr) {
    uint4 u;
    asm volatile("ld.shared.v4.u32 {%0,%1,%2,%3}, [%4];"
                 : "=r"(u.x), "=r"(u.y), "=r"(u.z), "=r"(u.w) : "r"(addr));
    return u;
}

// D(fp32) += A(bf16) * B(bf16), m16n8k16, A row-major frag, B col-major frag
__device__ __forceinline__ void mma_bf16(float* c, const uint32_t* a, const uint32_t* b) {
    asm volatile(
        "mma.sync.aligned.m16n8k16.row.col.f32.bf16.bf16.f32 "
        "{%0,%1,%2,%3}, {%4,%5,%6,%7}, {%8,%9}, {%0,%1,%2,%3};"
        : "+f"(c[0]), "+f"(c[1]), "+f"(c[2]), "+f"(c[3])
        : "r"(a[0]), "r"(a[1]), "r"(a[2]), "r"(a[3]), "r"(b[0]), "r"(b[1]));
}

// =============================================================== CSR build
__global__ void hist_kernel(const int* __restrict__ dst, int E) {
    int i = blockIdx.x * blockDim.x + threadIdx.x;
    if (i < E) atomicAdd(&g_deg[dst[i]], 1);
}

__global__ void scan_kernel(int E) {
    __shared__ int wsum[32];
    __shared__ int carry;
    if (threadIdx.x == 0) carry = 0;
    __syncthreads();
    int lane = threadIdx.x & 31, warp = threadIdx.x >> 5;
    for (int base = 0; base < NN; base += 1024) {
        int i = base + (int)threadIdx.x;
        int v = (i < NN) ? g_deg[i] : 0;
        int x = v;
        #pragma unroll
        for (int o = 1; o < 32; o <<= 1) {
            int y = __shfl_up_sync(0xffffffffu, x, o);
            if (lane >= o) x += y;
        }
        if (lane == 31) wsum[warp] = x;
        __syncthreads();
        if (warp == 0) {
            int t = wsum[lane];
            #pragma unroll
            for (int o = 1; o < 32; o <<= 1) {
                int y = __shfl_up_sync(0xffffffffu, t, o);
                if (lane >= o) t += y;
            }
            wsum[lane] = t;
        }
        __syncthreads();
        int incl = x + (warp > 0 ? wsum[warp - 1] : 0);
        int excl = carry + incl - v;
        if (i < NN) { g_off[i] = excl; g_cur[i] = excl; }
        __syncthreads();
        if (threadIdx.x == 1023) carry += incl;
        __syncthreads();
    }
    if (threadIdx.x == 0) g_off[NN] = E;
}

__global__ void scatter_kernel(const int* __restrict__ src,
                               const int* __restrict__ dst,
                               const float* __restrict__ val, int E) {
    int i = blockIdx.x * blockDim.x + threadIdx.x;
    if (i < E) {
        int p = atomicAdd(&g_cur[dst[i]], 1);
        g_epack[p] = make_int2(src[i], __float_as_int(val[i]));
    }
}

// =============================================================== fused prep
__global__ void prep_kernel(const float* __restrict__ x,
                            const float* __restrict__ W,
                            int n4, int npad) {
    int i = blockIdx.x * blockDim.x + threadIdx.x;
    if (i < n4) {
        float4 v = ((const float4*)x)[i];
        union { __nv_bfloat16 b[4]; uint2 u; } H, L;
        H.b[0] = __float2bfloat16(v.x); L.b[0] = __float2bfloat16(v.x - __bfloat162float(H.b[0]));
        H.b[1] = __float2bfloat16(v.y); L.b[1] = __float2bfloat16(v.y - __bfloat162float(H.b[1]));
        H.b[2] = __float2bfloat16(v.z); L.b[2] = __float2bfloat16(v.z - __bfloat162float(H.b[2]));
        H.b[3] = __float2bfloat16(v.w); L.b[3] = __float2bfloat16(v.w - __bfloat162float(H.b[3]));
        ((uint2*)g_xhi)[i] = H.u;
        ((uint2*)g_xlo)[i] = L.u;
    } else if (i < n4 + npad) {
        int p = i - n4;
        ((uint2*)g_xhi)[n4 + p] = make_uint2(0u, 0u);
        ((uint2*)g_xlo)[n4 + p] = make_uint2(0u, 0u);
    } else if (i < n4 + npad + CH * CH) {
        int t = i - n4 - npad;
        int k = t & (CH - 1);
        int n = t >> 8;
        float w = W[k * CH + n];
        __nv_bfloat16 h = __float2bfloat16(w);
        g_wthi[n * CH + k] = h;
        g_wtlo[n * CH + k] = __float2bfloat16(w - __bfloat162float(h));
    }
}

// =============================================================== mma.sync GEMM
#define SWZ(r, c) ((uint32_t)((r) * 64 + (((c) ^ ((r) & 3)) * 16)))
#define GEMM_SMEM 65536

__global__ __launch_bounds__(256, 2) void gemm_mma(int M, int bn) {
    extern __shared__ char smem[];
    const uint32_t sb = smem_u32(smem);
    const int tid  = threadIdx.x;
    const int lane = tid & 31;
    const int wid  = tid >> 5;
    const int warp_m = (wid & 3) * 32;
    const int warp_n = (wid >> 2) * 64;
    const size_t arow = (size_t)blockIdx.x * 128;

    float acc[2][8][4];
    #pragma unroll
    for (int mt = 0; mt < 2; mt++)
        #pragma unroll
        for (int nt = 0; nt < 8; nt++)
            #pragma unroll
            for (int j = 0; j < 4; j++) acc[mt][nt][j] = 0.f;

    auto fill = [&](int buf, int ch) {
        const int k0 = ch * 32;
        const uint32_t base = sb + buf * 32768;
        #pragma unroll
        for (int i = 0; i < 2; i++) {
            int chunk = tid + i * 256;
            int r = chunk >> 2, c = chunk & 3;
            uint32_t so = SWZ(r, c);
            size_t ga = (arow + r) * CH + k0 + c * 8;
            size_t gb = (size_t)(bn + r) * CH + k0 + c * 8;
            cp_async16(base +     0 + so, &g_xhi[ga]);
            cp_async16(base +  8192 + so, &g_xlo[ga]);
            cp_async16(base + 16384 + so, &g_wthi[gb]);
            cp_async16(base + 24576 + so, &g_wtlo[gb]);
        }
    };

    auto compute = [&](int buf) {
        const uint32_t base = sb + buf * 32768;
        #pragma unroll
        for (int ks = 0; ks < 2; ks++) {
            uint32_t a_hi[2][4], a_lo[2][4];
            const int achunk = 2 * ks + (lane >> 4);
            #pragma unroll
            for (int mt = 0; mt < 2; mt++) {
                int r = warp_m + mt * 16 + (lane & 15);
                uint32_t ad = base + SWZ(r, achunk);
                ldsm_x4(a_hi[mt], ad);
                ldsm_x4(a_lo[mt], ad + 8192);
            }
            #pragma unroll
            for (int np = 0; np < 4; np++) {
                int nr = warp_n + np * 16 + (lane & 7) + ((lane & 16) ? 8 : 0);
                int bchunk = 2 * ks + ((lane >> 3) & 1);
                uint32_t bd = base + 16384 + SWZ(nr, bchunk);
                uint32_t bhi[4], blo[4];
                ldsm_x4(bhi, bd);
                ldsm_x4(blo, bd + 8192);
                #pragma unroll
                for (int h = 0; h < 2; h++) {
                    int nt = np * 2 + h;
                    #pragma unroll
                    for (int mt = 0; mt < 2; mt++) {
                        mma_bf16(acc[mt][nt], a_hi[mt], &bhi[2 * h]);
                        mma_bf16(acc[mt][nt], a_hi[mt], &blo[2 * h]);
                        mma_bf16(acc[mt][nt], a_lo[mt], &bhi[2 * h]);
                    }
                }
            }
        }
    };

    fill(0, 0);
    cp_commit();
    #pragma unroll 1
    for (int ch = 0; ch < 8; ch++) {
        if (ch < 7) {
            fill((ch + 1) & 1, ch + 1);
            cp_commit();
            cp_wait<1>();
        } else {
            cp_wait<0>();
        }
        __syncthreads();
        compute(ch & 1);
        __syncthreads();
    }

    #pragma unroll
    for (int mt = 0; mt < 2; mt++) {
        size_t r0 = arow + warp_m + mt * 16 + (lane >> 2);
        #pragma unroll
        for (int nt = 0; nt < 8; nt++) {
            int gc = bn + warp_n + nt * 8 + 2 * (lane & 3);
            if (r0 < (size_t)M)
                *(__half2*)&g_xwh[r0 * CH + gc] =
                    __floats2half2_rn(acc[mt][nt][0], acc[mt][nt][1]);
            if (r0 + 8 < (size_t)M)
                *(__half2*)&g_xwh[(r0 + 8) * CH + gc] =
                    __floats2half2_rn(acc[mt][nt][2], acc[mt][nt][3]);
        }
    }
}

// =============================================================== gather
// cp.async-staged: each thread copies ITS 16 bytes of each edge row into a
// thread-private SMEM slot (no barriers — producer == consumer), 8 edges per
// stage, double-buffered. LDGSTS has no scoreboard/register MLP limit, so the
// L2 latency and L1tex-queue contention of the batched-LDG version vanish.
// 16 threads x 8ch per node, 16 nodes per 256-thread block.
#define GSTG 2048                         // 8 edges * 256B, per group per stage
#define GATHER_SMEM (16 * 2 * GSTG)       // 64 KB

__global__ __launch_bounds__(256) void gather_half(const float* __restrict__ bias,
                                                   float* __restrict__ out, int c0) {
    extern __shared__ char gsm[];
    int grp = threadIdx.x >> 4;
    int lt  = threadIdx.x & 15;
    int node = blockIdx.x * 16 + grp;
    if (node >= NN) return;
    int c = c0 + (lt << 3);               // 8 halves per thread
    int s = g_off[node], e = g_off[node + 1];

    float acc[8];
    #pragma unroll
    for (int j = 0; j < 8; j++) acc[j] = bias[c + j];

    auto fma8 = [&](float v, uint4 u) {
        const __half2* h = (const __half2*)&u;
        #pragma unroll
        for (int q = 0; q < 4; q++) {
            float2 f = __half22float2(h[q]);
            acc[2 * q]     += v * f.x;
            acc[2 * q + 1] += v * f.y;
        }
    };

    if (s < e) {
        const __half* __restrict__ xw = g_xwh;
        const uint32_t st0 = smem_u32(gsm) + grp * (2 * GSTG) + lt * 16;
        const uint32_t st1 = st0 + GSTG;
        int2 m0[8], m1[8];

        auto meta0 = [&](int j) {
            #pragma unroll
            for (int q = 0; q < 8; q++) {
                int idx = j + q; if (idx >= e) idx = e - 1;
                m0[q] = __ldg(&g_epack[idx]);
            }
        };
        auto meta1 = [&](int j) {
            #pragma unroll
            for (int q = 0; q < 8; q++) {
                int idx = j + q; if (idx >= e) idx = e - 1;
                m1[q] = __ldg(&g_epack[idx]);
            }
        };
        auto issue0 = [&]() {
            #pragma unroll
            for (int q = 0; q < 8; q++)
                cp_async16(st0 + q * 256, &xw[(size_t)m0[q].x * CH + c]);
            cp_commit();
        };
        auto issue1 = [&]() {
            #pragma unroll
            for (int q = 0; q < 8; q++)
                cp_async16(st1 + q * 256, &xw[(size_t)m1[q].x * CH + c]);
            cp_commit();
        };
        auto consume0 = [&](int j) {
            #pragma unroll
            for (int q = 0; q < 8; q++) {
                uint4 u = lds128(st0 + q * 256);
                float v = (j + q < e) ? __int_as_float(m0[q].y) : 0.f;
                fma8(v, u);
            }
        };
        auto consume1 = [&](int j) {
            #pragma unroll
            for (int q = 0; q < 8; q++) {
                uint4 u = lds128(st1 + q * 256);
                float v = (j + q < e) ? __int_as_float(m1[q].y) : 0.f;
                fma8(v, u);
            }
        };

        int j = s;
        meta0(j); issue0();
        int jn = j + 8;
        while (true) {
            if (jn < e) { meta1(jn); issue1(); cp_wait<1>(); }
            else        { cp_wait<0>(); }
            consume0(j);
            if (jn >= e) break;
            j = jn; jn += 8;
            if (jn < e) { meta0(jn); issue0(); cp_wait<1>(); }
            else        { cp_wait<0>(); }
            consume1(j);
            if (jn >= e) break;
            j = jn; jn += 8;
        }
    }

    float4 o0 = make_float4(acc[0], acc[1], acc[2], acc[3]);
    float4 o1 = make_float4(acc[4], acc[5], acc[6], acc[7]);
    *(float4*)&out[(size_t)node * CH + c]     = o0;
    *(float4*)&out[(size_t)node * CH + c + 4] = o1;
}

// =============================================================== launch
// DAG identical to R12 (measured best):
//   main:  prep(fused) -> gemm(n=0..127) -> gemm(n=128..255)
//   sB:    memset(deg) -> hist -> scan -> scatter
//   sC(hi):[gemm0 && scatter] -> gather cols 0..127
//   main:  [gemm1 && scatter] -> gather cols 128..255 -> join sC
extern "C" void kernel_launch(void* const* d_in, const int* in_sizes, int n_in,
                              void* d_out, int out_size) {
    const float* x    = (const float*)d_in[0];   // [N, 256]
    const float* W    = (const float*)d_in[1];   // [256, 256]
    const float* bias = (const float*)d_in[2];   // [256]
    const int*   esrc = (const int*)d_in[3];     // [E]
    const int*   edst = (const int*)d_in[4];     // [E]
    const float* eval = (const float*)d_in[5];   // [E]
    float* out = (float*)d_out;

    int M = in_sizes[0] / CH;   // 50000
    int E = in_sizes[3];        // 800000

    cudaFuncSetAttribute(gemm_mma, cudaFuncAttributeMaxDynamicSharedMemorySize,
                         GEMM_SMEM);
    cudaFuncSetAttribute(gather_half, cudaFuncAttributeMaxDynamicSharedMemorySize,
                         GATHER_SMEM);

    int prLow = 0, prHigh = 0;
    cudaDeviceGetStreamPriorityRange(&prLow, &prHigh);

    cudaStream_t sB, sC;
    cudaStreamCreateWithFlags(&sB, cudaStreamNonBlocking);
    cudaStreamCreateWithPriority(&sC, cudaStreamNonBlocking, prHigh);
    cudaEvent_t evRoot, evS, evG0, evC;
    cudaEventCreateWithFlags(&evRoot, cudaEventDisableTiming);
    cudaEventCreateWithFlags(&evS,    cudaEventDisableTiming);
    cudaEventCreateWithFlags(&evG0,   cudaEventDisableTiming);
    cudaEventCreateWithFlags(&evC,    cudaEventDisableTiming);

    // fork sB off the (captured) default stream
    cudaEventRecord(evRoot, 0);
    cudaStreamWaitEvent(sB, evRoot, 0);

    // ---- branch B: CSR-by-dst build ----
    void* degp = nullptr;
    cudaGetSymbolAddress(&degp, g_deg);
    cudaMemsetAsync(degp, 0, NN * sizeof(int), sB);
    hist_kernel<<<(E + 255) / 256, 256, 0, sB>>>(edst, E);
    scan_kernel<<<1, 1024, 0, sB>>>(E);
    scatter_kernel<<<(E + 255) / 256, 256, 0, sB>>>(esrc, edst, eval, E);
    cudaEventRecord(evS, sB);

    // ---- main branch: fused prep + GEMM halves ----
    int n4 = (M * CH) / 4;
    int npad = ((PAD_M - M) * CH) / 4;
    int ptotal = n4 + npad + CH * CH;
    prep_kernel<<<(ptotal + 255) / 256, 256>>>(x, W, n4, npad);
    int mblk = (M + 127) / 128;   // 391
    gemm_mma<<<mblk, 256, GEMM_SMEM>>>(M, 0);
    cudaEventRecord(evG0, 0);
    gemm_mma<<<mblk, 256, GEMM_SMEM>>>(M, 128);

    // ---- branch C (high priority): gather cols 0..127, overlaps gemm1 ----
    cudaStreamWaitEvent(sC, evG0, 0);
    cudaStreamWaitEvent(sC, evS, 0);
    gather_half<<<(NN + 15) / 16, 256, GATHER_SMEM, sC>>>(bias, out, 0);
    cudaEventRecord(evC, sC);

    // ---- main branch: gather cols 128..255, then join everything ----
    cudaStreamWaitEvent(0, evS, 0);
    gather_half<<<(NN + 15) / 16, 256, GATHER_SMEM>>>(bias, out, 128);
    cudaStreamWaitEvent(0, evC, 0);

    cudaEventDestroy(evRoot);
    cudaEventDestroy(evS);
    cudaEventDestroy(evG0);
    cudaEventDestroy(evC);
    cudaStreamDestroy(sB);
    cudaStreamDestroy(sC);
}

// round 14
// speedup vs baseline: 1.1612x; 1.1612x over previous
#include <cuda_runtime.h>
#include <cuda_fp16.h>
#include <cstdint>

#define NN 50000
#define EE 800000
#define CH 256

// ---- scratch (device globals; no allocation allowed) ----
__device__ __align__(16) __half g_xwh[(size_t)NN * CH];    // x @ W (25.6 MB, fp16)
__device__ int   g_deg[NN];
__device__ int   g_off[NN + 1];
__device__ int   g_cur[NN];
__device__ __align__(16) int2  g_epack[EE];                // (src, val)
__device__ __align__(16) float g_wtf[CH * CH];             // W^T fp32 [n][k]

// =============================================================== helpers
__device__ __forceinline__ uint32_t smem_u32(const void* p) {
    uint32_t a;
    asm("{ .reg .u64 t; cvta.to.shared.u64 t, %1; cvt.u32.u64 %0, t; }"
        : "=r"(a) : "l"(p));
    return a;
}

__device__ __forceinline__ void cp_async16(uint32_t s, const void* g) {
    asm volatile("cp.async.cg.shared.global [%0], [%1], 16;" :: "r"(s), "l"(g));
}
// src-size variant: sz==0 -> pure zero-fill
__device__ __forceinline__ void cp_async16z(uint32_t s, const void* g, unsigned sz) {
    asm volatile("cp.async.cg.shared.global [%0], [%1], 16, %2;"
                 :: "r"(s), "l"(g), "r"(sz));
}
__device__ __forceinline__ void cp_commit() {
    asm volatile("cp.async.commit_group;" ::: "memory");
}
template <int N>
__device__ __forceinline__ void cp_wait() {
    asm volatile("cp.async.wait_group %0;" :: "n"(N) : "memory");
}

__device__ __forceinline__ uint32_t lds32(uint32_t addr) {
    uint32_t u;
    asm volatile("ld.shared.b32 %0, [%1];" : "=r"(u) : "r"(addr));
    return u;
}

__device__ __forceinline__ uint32_t f2tf32(uint32_t bits) {
    float v = __uint_as_float(bits);
    uint32_t t;
    asm("cvt.rna.tf32.f32 %0, %1;" : "=r"(t) : "f"(v));
    return t;
}

// D(fp32) += A(tf32) * B(tf32), m16n8k8, A row-major frag, B col-major frag
__device__ __forceinline__ void mma_tf32(float* c, const uint32_t* a, const uint32_t* b) {
    asm volatile(
        "mma.sync.aligned.m16n8k8.row.col.f32.tf32.tf32.f32 "
        "{%0,%1,%2,%3}, {%4,%5,%6,%7}, {%8,%9}, {%0,%1,%2,%3};"
        : "+f"(c[0]), "+f"(c[1]), "+f"(c[2]), "+f"(c[3])
        : "r"(a[0]), "r"(a[1]), "r"(a[2]), "r"(a[3]), "r"(b[0]), "r"(b[1]));
}

// =============================================================== CSR build
__global__ void hist_kernel(const int* __restrict__ dst, int E) {
    int i = blockIdx.x * blockDim.x + threadIdx.x;
    if (i < E) atomicAdd(&g_deg[dst[i]], 1);
}

__global__ void scan_kernel(int E) {
    __shared__ int wsum[32];
    __shared__ int carry;
    if (threadIdx.x == 0) carry = 0;
    __syncthreads();
    int lane = threadIdx.x & 31, warp = threadIdx.x >> 5;
    for (int base = 0; base < NN; base += 1024) {
        int i = base + (int)threadIdx.x;
        int v = (i < NN) ? g_deg[i] : 0;
        int x = v;
        #pragma unroll
        for (int o = 1; o < 32; o <<= 1) {
            int y = __shfl_up_sync(0xffffffffu, x, o);
            if (lane >= o) x += y;
        }
        if (lane == 31) wsum[warp] = x;
        __syncthreads();
        if (warp == 0) {
            int t = wsum[lane];
            #pragma unroll
            for (int o = 1; o < 32; o <<= 1) {
                int y = __shfl_up_sync(0xffffffffu, t, o);
                if (lane >= o) t += y;
            }
            wsum[lane] = t;
        }
        __syncthreads();
        int incl = x + (warp > 0 ? wsum[warp - 1] : 0);
        int excl = carry + incl - v;
        if (i < NN) { g_off[i] = excl; g_cur[i] = excl; }
        __syncthreads();
        if (threadIdx.x == 1023) carry += incl;
        __syncthreads();
    }
    if (threadIdx.x == 0) g_off[NN] = E;
}

__global__ void scatter_kernel(const int* __restrict__ src,
                               const int* __restrict__ dst,
                               const float* __restrict__ val, int E) {
    int i = blockIdx.x * blockDim.x + threadIdx.x;
    if (i < E) {
        int p = atomicAdd(&g_cur[dst[i]], 1);
        g_epack[p] = make_int2(src[i], __float_as_int(val[i]));
    }
}

// =============================================================== W transpose
// g_wtf[n][k] = W[k][n], tiled via SMEM (coalesced both sides). 256 KB total.
__global__ void wt_kernel(const float* __restrict__ W) {
    __shared__ float t[32][33];
    int bx = blockIdx.x * 32, by = blockIdx.y * 32;   // bx: k-base, by: n-base
    int tx = threadIdx.x, ty = threadIdx.y;
    #pragma unroll
    for (int r = 0; r < 32; r += 8)
        t[ty + r][tx] = W[(size_t)(bx + ty + r) * CH + by + tx];
    __syncthreads();
    #pragma unroll
    for (int r = 0; r < 32; r += 8)
        g_wtf[(size_t)(by + ty + r) * CH + bx + tx] = t[tx][ty + r];
}

// =============================================================== tf32 GEMM
// g_xwh[M, bn..bn+127] = x @ W[:, bn..bn+127], tf32 mma, fp32 accum, fp16 out.
// CTA tile 128m x 128n, BK=32, cp.async double buffer, 8 warps (4m x 2n),
// warp tile 32m x 64n = 2 m16 x 8 n8 tiles, K per mma = 8.
// SMEM per buffer: A fp32 128x32 (16K) | B fp32 128x32 (16K); x2 = 64 KB.
// Tile rows are 128B (32 floats); 16B chunk swizzle: chunk ^= (row & 7).
#define GEMM_SMEM 65536

__global__ __launch_bounds__(256, 2) void gemm_mma(const float* __restrict__ x,
                                                   int M, int bn) {
    extern __shared__ char smem[];
    const uint32_t sb = smem_u32(smem);
    const int tid  = threadIdx.x;
    const int lane = tid & 31;
    const int wid  = tid >> 5;
    const int warp_m = (wid & 3) * 32;   // 0,32,64,96
    const int warp_n = (wid >> 2) * 64;  // 0,64
    const size_t arow = (size_t)blockIdx.x * 128;
    const int g  = lane >> 2;            // 0..7
    const int t4 = lane & 3;             // 0..3

    float acc[2][8][4];
    #pragma unroll
    for (int mt = 0; mt < 2; mt++)
        #pragma unroll
        for (int nt = 0; nt < 8; nt++)
            #pragma unroll
            for (int j = 0; j < 4; j++) acc[mt][nt][j] = 0.f;

    // addr of float (r, k) within a tile: r*128 + ((k/4 ^ (r&7))*16) + (k&3)*4
    auto taddr = [](uint32_t base, int r, int k) {
        return base + (uint32_t)(r * 128 + (((k >> 2) ^ (r & 7)) * 16) + (k & 3) * 4);
    };

    auto fill = [&](int buf, int ch) {
        const int k0 = ch * 32;
        const uint32_t base = sb + buf * 32768;
        #pragma unroll
        for (int i = 0; i < 4; i++) {
            int chunk = tid + i * 256;          // 0..1023
            int r = chunk >> 3, c = chunk & 7;  // row, 16B-chunk (4 floats)
            uint32_t so = (uint32_t)(r * 128 + ((c ^ (r & 7)) * 16));
            size_t grow = arow + r;
            bool ok = grow < (size_t)M;
            cp_async16z(base + so, &x[(ok ? grow : 0) * CH + k0 + 4 * c], ok ? 16u : 0u);
            cp_async16(base + 16384 + so, &g_wtf[(size_t)(bn + r) * CH + k0 + 4 * c]);
        }
    };

    auto compute = [&](int buf) {
        const uint32_t abase = sb + buf * 32768;
        const uint32_t bbase = abase + 16384;
        #pragma unroll
        for (int ks = 0; ks < 4; ks++) {
            const int kk = ks * 8 + t4;         // k and k+4 within BK=32
            uint32_t a[2][4];
            #pragma unroll
            for (int mt = 0; mt < 2; mt++) {
                int r0 = warp_m + mt * 16 + g;
                a[mt][0] = f2tf32(lds32(taddr(abase, r0,     kk)));
                a[mt][1] = f2tf32(lds32(taddr(abase, r0 + 8, kk)));
                a[mt][2] = f2tf32(lds32(taddr(abase, r0,     kk + 4)));
                a[mt][3] = f2tf32(lds32(taddr(abase, r0 + 8, kk + 4)));
            }
            #pragma unroll
            for (int nt = 0; nt < 8; nt++) {
                int nr = warp_n + nt * 8 + g;
                uint32_t b[2];
                b[0] = f2tf32(lds32(taddr(bbase, nr, kk)));
                b[1] = f2tf32(lds32(taddr(bbase, nr, kk + 4)));
                mma_tf32(acc[0][nt], a[0], b);
                mma_tf32(acc[1][nt], a[1], b);
            }
        }
    };

    fill(0, 0);
    cp_commit();
    #pragma unroll 1
    for (int ch = 0; ch < 8; ch++) {
        if (ch < 7) {
            fill((ch + 1) & 1, ch + 1);
            cp_commit();
            cp_wait<1>();
        } else {
            cp_wait<0>();
        }
        __syncthreads();
        compute(ch & 1);
        __syncthreads();
    }

    // epilogue: fp32 acc -> fp16 xw  (c0,c1: row g, cols 2t4..; c2,c3: row g+8)
    #pragma unroll
    for (int mt = 0; mt < 2; mt++) {
        size_t r0 = arow + warp_m + mt * 16 + g;
        #pragma unroll
        for (int nt = 0; nt < 8; nt++) {
            int gc = bn + warp_n + nt * 8 + 2 * t4;
            if (r0 < (size_t)M)
                *(__half2*)&g_xwh[r0 * CH + gc] =
                    __floats2half2_rn(acc[mt][nt][0], acc[mt][nt][1]);
            if (r0 + 8 < (size_t)M)
                *(__half2*)&g_xwh[(r0 + 8) * CH + gc] =
                    __floats2half2_rn(acc[mt][nt][2], acc[mt][nt][3]);
        }
    }
}

// =============================================================== gather
// (measured-best R12 version) out[d][c0+c..] = b + sum val * xwh[src][..]
// fp16 reads, fp32 accum; 16 threads x 8ch per node, 16 nodes per block;
// fully predicated batch-8 (tail clamps index, zeroes weight).
__global__ __launch_bounds__(256) void gather_half(const float* __restrict__ bias,
                                                   float* __restrict__ out, int c0) {
    int node = blockIdx.x * 16 + (threadIdx.x >> 4);
    if (node >= NN) return;
    int c = c0 + ((threadIdx.x & 15) << 3);
    int s = g_off[node], e = g_off[node + 1];

    float acc[8];
    #pragma unroll
    for (int j = 0; j < 8; j++) acc[j] = bias[c + j];

    auto fma8 = [&](float v, uint4 u) {
        const __half2* h = (const __half2*)&u;
        #pragma unroll
        for (int q = 0; q < 4; q++) {
            float2 f = __half22float2(h[q]);
            acc[2 * q]     += v * f.x;
            acc[2 * q + 1] += v * f.y;
        }
    };

    const __half* __restrict__ xw = g_xwh;
    for (int j = s; j < e; j += 8) {
        int2 m[8];
        #pragma unroll
        for (int q = 0; q < 8; q++) {
            int idx = j + q;
            if (idx >= e) idx = e - 1;
            m[q] = __ldg(&g_epack[idx]);
        }
        uint4 xv[8];
        #pragma unroll
        for (int q = 0; q < 8; q++)
            xv[q] = __ldg((const uint4*)&xw[(size_t)m[q].x * CH + c]);
        #pragma unroll
        for (int q = 0; q < 8; q++) {
            float v = (j + q < e) ? __int_as_float(m[q].y) : 0.f;
            fma8(v, xv[q]);
        }
    }

    float4 o0 = make_float4(acc[0], acc[1], acc[2], acc[3]);
    float4 o1 = make_float4(acc[4], acc[5], acc[6], acc[7]);
    *(float4*)&out[(size_t)node * CH + c]     = o0;
    *(float4*)&out[(size_t)node * CH + c + 4] = o1;
}

// =============================================================== launch
// DAG identical to the measured-best R12 structure:
//   main:  wt_transpose -> gemm(n=0..127) -> gemm(n=128..255)
//   sB:    memset(deg) -> hist -> scan -> scatter
//   sC(hi):[gemm0 && scatter] -> gather cols 0..127
//   main:  [gemm1 && scatter] -> gather cols 128..255 -> join sC
extern "C" void kernel_launch(void* const* d_in, const int* in_sizes, int n_in,
                              void* d_out, int out_size) {
    const float* x    = (const float*)d_in[0];   // [N, 256]
    const float* W    = (const float*)d_in[1];   // [256, 256]
    const float* bias = (const float*)d_in[2];   // [256]
    const int*   esrc = (const int*)d_in[3];     // [E]
    const int*   edst = (const int*)d_in[4];     // [E]
    const float* eval = (const float*)d_in[5];   // [E]
    float* out = (float*)d_out;

    int M = in_sizes[0] / CH;   // 50000
    int E = in_sizes[3];        // 800000

    cudaFuncSetAttribute(gemm_mma, cudaFuncAttributeMaxDynamicSharedMemorySize,
                         GEMM_SMEM);

    int prLow = 0, prHigh = 0;
    cudaDeviceGetStreamPriorityRange(&prLow, &prHigh);

    cudaStream_t sB, sC;
    cudaStreamCreateWithFlags(&sB, cudaStreamNonBlocking);
    cudaStreamCreateWithPriority(&sC, cudaStreamNonBlocking, prHigh);
    cudaEvent_t evRoot, evS, evG0, evC;
    cudaEventCreateWithFlags(&evRoot, cudaEventDisableTiming);
    cudaEventCreateWithFlags(&evS,    cudaEventDisableTiming);
    cudaEventCreateWithFlags(&evG0,   cudaEventDisableTiming);
    cudaEventCreateWithFlags(&evC,    cudaEventDisableTiming);

    // fork sB off the (captured) default stream
    cudaEventRecord(evRoot, 0);
    cudaStreamWaitEvent(sB, evRoot, 0);

    // ---- branch B: CSR-by-dst build ----
    void* degp = nullptr;
    cudaGetSymbolAddress(&degp, g_deg);
    cudaMemsetAsync(degp, 0, NN * sizeof(int), sB);
    hist_kernel<<<(E + 255) / 256, 256, 0, sB>>>(edst, E);
    scan_kernel<<<1, 1024, 0, sB>>>(E);
    scatter_kernel<<<(E + 255) / 256, 256, 0, sB>>>(esrc, edst, eval, E);
    cudaEventRecord(evS, sB);

    // ---- main branch: W transpose + tf32 GEMM halves ----
    dim3 wtb(32, 8);
    dim3 wtg(CH / 32, CH / 32);
    wt_kernel<<<wtg, wtb>>>(W);
    int mblk = (M + 127) / 128;   // 391
    gemm_mma<<<mblk, 256, GEMM_SMEM>>>(x, M, 0);
    cudaEventRecord(evG0, 0);
    gemm_mma<<<mblk, 256, GEMM_SMEM>>>(x, M, 128);

    // ---- branch C (high priority): gather cols 0..127, overlaps gemm1 ----
    cudaStreamWaitEvent(sC, evG0, 0);
    cudaStreamWaitEvent(sC, evS, 0);
    gather_half<<<(NN + 15) / 16, 256, 0, sC>>>(bias, out, 0);
    cudaEventRecord(evC, sC);

    // ---- main branch: gather cols 128..255, then join everything ----
    cudaStreamWaitEvent(0, evS, 0);
    gather_half<<<(NN + 15) / 16, 256>>>(bias, out, 128);
    cudaStreamWaitEvent(0, evC, 0);

    cudaEventDestroy(evRoot);
    cudaEventDestroy(evS);
    cudaEventDestroy(evG0);
    cudaEventDestroy(evC);
    cudaStreamDestroy(sB);
    cudaStreamDestroy(sC);
}